// round 10
// baseline (speedup 1.0000x reference)
#include <cuda_runtime.h>
#include <cuda_bf16.h>

// Problem constants
#define BB 8
#define NN 512
#define DD 64
#define EE 32

// Scratch (allocation-free rule -> __device__ global)
// layout [e][b][j] so per-j reads in the final kernel are coalesced per e
__device__ float g_part[EE * BB * NN];

// ---------------------------------------------------------------------------
// Kernel 1: one block per (b,e), 512 threads (thread t = row index i AND
// query index j).
//   1. stage We columns (src col e, dst col e) in smem
//   2. thread t: s_t = x[b,t,:]·Wsrc_e ;  d_t = x[b,t,:]·Wdst_e + be[e]
//   3. bitonic sort (s, w) pairs ascending by s   (w_t = Wr[t*E+e])
//   4. suffix scans  SW[k] = sum_{m>=k} w_m,  SSW[k] = sum_{m>=k} s_m*w_m
//   5. thread t: binary search k = first index with s_sorted[k] > -d_t
//      c = SSW[k] + d_t * SW[k]     ( = sum_i relu(s_i + d_t) * w_i exactly )
//   6. g_part[e][b][t] = c          (coalesced)
// ---------------------------------------------------------------------------
__global__ __launch_bounds__(512) void sortsum_kernel(
    const float* __restrict__ x,
    const float* __restrict__ We,
    const float* __restrict__ be,
    const float* __restrict__ Wr)
{
    __shared__ float s_s[NN];        // sorted keys (kept for binsearch)
    __shared__ float w_s[NN];        // weights, permuted with keys
    __shared__ float A  [NN];        // suffix sum of w
    __shared__ float Bv [NN];        // suffix sum of s*w
    __shared__ float wecol[2 * DD];  // We column e: [0:64) src, [64:128) dst

    const int tid = threadIdx.x;
    const int b   = blockIdx.x >> 5;     // adjacent blocks share x[b] in L2
    const int e   = blockIdx.x & 31;

    if (tid < 2 * DD) wecol[tid] = We[tid * EE + e];
    __syncthreads();

    // ---- projections for this thread's row ----
    const float4* xr = (const float4*)(x + (b * NN + tid) * DD);
    float s_acc = 0.0f;
    float d_acc = be[e];
    #pragma unroll
    for (int q = 0; q < DD / 4; q++) {
        float4 v  = xr[q];                                // 16 LDG.128, MLP'd
        float4 ws = *(const float4*)&wecol[q * 4];        // broadcast LDS.128
        float4 wd = *(const float4*)&wecol[DD + q * 4];
        s_acc = fmaf(v.x, ws.x, s_acc); s_acc = fmaf(v.y, ws.y, s_acc);
        s_acc = fmaf(v.z, ws.z, s_acc); s_acc = fmaf(v.w, ws.w, s_acc);
        d_acc = fmaf(v.x, wd.x, d_acc); d_acc = fmaf(v.y, wd.y, d_acc);
        d_acc = fmaf(v.z, wd.z, d_acc); d_acc = fmaf(v.w, wd.w, d_acc);
    }
    const float w_t = Wr[tid * EE + e];

    s_s[tid] = s_acc;
    w_s[tid] = w_t;

    // ---- bitonic sort ascending by s (45 phases) ----
    #pragma unroll 1
    for (int k = 2; k <= NN; k <<= 1) {
        #pragma unroll 1
        for (int jj = k >> 1; jj > 0; jj >>= 1) {
            __syncthreads();
            const int l = tid ^ jj;
            if (l > tid) {
                const float sa = s_s[tid], sb = s_s[l];
                const bool up = ((tid & k) == 0);
                if ((sa > sb) == up) {
                    s_s[tid] = sb; s_s[l] = sa;
                    const float wa = w_s[tid], wb = w_s[l];
                    w_s[tid] = wb; w_s[l] = wa;
                }
            }
        }
    }
    __syncthreads();

    // ---- suffix scans (Hillis-Steele, inclusive from the right) ----
    {
        const float sv = s_s[tid], wv = w_s[tid];
        A [tid] = wv;
        Bv[tid] = sv * wv;
    }
    __syncthreads();
    #pragma unroll 1
    for (int off = 1; off < NN; off <<= 1) {
        const float ta = (tid + off < NN) ? A [tid + off] : 0.0f;
        const float tb = (tid + off < NN) ? Bv[tid + off] : 0.0f;
        __syncthreads();
        A [tid] += ta;
        Bv[tid] += tb;
        __syncthreads();
    }

    // ---- binary search: first k with s_sorted[k] > -d ----
    const float target = -d_acc;
    int lo = 0, hi = NN;
    while (lo < hi) {
        const int mid = (lo + hi) >> 1;
        if (s_s[mid] > target) hi = mid; else lo = mid + 1;
    }

    const float c = (lo < NN) ? fmaf(d_acc, A[lo], Bv[lo]) : 0.0f;
    g_part[(e * BB + b) * NN + tid] = c;      // coalesced (consecutive tid)
}

// ---------------------------------------------------------------------------
// Kernel 2: out[b,j] = sum_e g_part[e][b][j] + br
// 16 blocks x 256 threads; each e-iteration is a coalesced 128B read.
// ---------------------------------------------------------------------------
__global__ __launch_bounds__(256) void final_reduce_kernel(
    const float* __restrict__ br,
    float* __restrict__ out)
{
    const int idx = blockIdx.x * 256 + threadIdx.x;   // b*N + j, 0..4095
    const int b = idx >> 9;
    const int j = idx & (NN - 1);

    float acc = br[0];
    #pragma unroll
    for (int e = 0; e < EE; e++)
        acc += g_part[(e * BB + b) * NN + j];
    out[idx] = acc;
}

// ---------------------------------------------------------------------------
// launch
// ---------------------------------------------------------------------------
extern "C" void kernel_launch(void* const* d_in, const int* in_sizes, int n_in,
                              void* d_out, int out_size)
{
    const float* x  = (const float*)d_in[0];   // (8,512,64)
    const float* We = (const float*)d_in[1];   // (128,32)
    const float* be = (const float*)d_in[2];   // (32,)
    const float* Wr = (const float*)d_in[3];   // (16384,1)
    const float* br = (const float*)d_in[4];   // (1,)
    float* out = (float*)d_out;                // (8,512,1)

    sortsum_kernel<<<BB * EE, 512>>>(x, We, be, Wr);
    final_reduce_kernel<<<BB * NN / 256, 256>>>(br, out);
}

// round 11
// speedup vs baseline: 1.4332x; 1.4332x over previous
#include <cuda_runtime.h>
#include <cuda_bf16.h>

// Problem constants
#define BB 8
#define NN 512
#define DD 64
#define EE 32

#define JT 64                 // edge: j's per block (8 warps x 8 j)
#define SS 8                  // i-splits
#define IT (NN / SS)          // 64 i-rows per block
#define BLOCKS_PER_B (SS * (NN / JT))   // 64 edge blocks per batch b... (8*8=64)? -> 8 jb * 8 s = 64

#define RPB 16                // proj: x-rows per block
#define RPW 4                 // proj: rows per warp

// Scratch (allocation-free rule -> __device__ globals)
__device__ float g_src [BB * NN * EE];        // src[b,n,e]
__device__ float g_dstb[BB * NN * EE];        // dst[b,n,e] + be[e]
__device__ float g_part[BB * NN * SS];        // partial[b,j,s]
__device__ unsigned int g_done[BB];           // monotonic completion counters

// ---- packed fp32 pair helpers (sm_103a FADD2/FFMA2 via PTX f32x2) ----------
union F2U { unsigned long long u; float2 f; };

__device__ __forceinline__ unsigned long long add2(unsigned long long a,
                                                   unsigned long long b) {
    unsigned long long r;
    asm("add.rn.f32x2 %0, %1, %2;" : "=l"(r) : "l"(a), "l"(b));
    return r;
}
__device__ __forceinline__ unsigned long long fma2(unsigned long long a,
                                                   unsigned long long b,
                                                   unsigned long long c) {
    unsigned long long r;
    asm("fma.rn.f32x2 %0, %1, %2, %3;" : "=l"(r) : "l"(a), "l"(b), "l"(c));
    return r;
}

// ---------------------------------------------------------------------------
// Kernel 1 (R4 exact): src = x @ We[:D], dstb = x @ We[D:] + be
// ---------------------------------------------------------------------------
__global__ __launch_bounds__(256) void proj_kernel(
    const float* __restrict__ x,
    const float* __restrict__ We,
    const float* __restrict__ be)
{
    const int row0 = blockIdx.x * RPB;
    __shared__ float xs [RPB][DD];              // 4 KB
    __shared__ float Wsh[2 * DD][EE];           // 16 KB

    const int tid = threadIdx.x;
    #pragma unroll
    for (int k = 0; k < 4; k++)
        ((float4*)Wsh)[k * 256 + tid] = ((const float4*)We)[k * 256 + tid];
    ((float4*)xs)[tid] = ((const float4*)(x + row0 * DD))[tid];
    __syncthreads();

    const int lane = tid & 31;                  // = e
    const int w    = tid >> 5;
    const int half = w >> 2;                    // 0 = src, 1 = dst
    const int r0   = (w & 3) * RPW;

    const float* Wh = &Wsh[half * DD][0];
    const float bias = half ? be[lane] : 0.0f;

    float acc[RPW];
    #pragma unroll
    for (int r = 0; r < RPW; r++) acc[r] = bias;

    #pragma unroll
    for (int d4 = 0; d4 < DD; d4 += 4) {
        float4 xv[RPW];
        #pragma unroll
        for (int r = 0; r < RPW; r++)
            xv[r] = *(const float4*)&xs[r0 + r][d4];
        #pragma unroll
        for (int k = 0; k < 4; k++) {
            float wv = Wh[(d4 + k) * EE + lane];
            #pragma unroll
            for (int r = 0; r < RPW; r++)
                acc[r] = fmaf((&xv[r].x)[k], wv, acc[r]);
        }
    }

    float* dst = half ? g_dstb : g_src;
    #pragma unroll
    for (int r = 0; r < RPW; r++)
        dst[(row0 + r0 + r) * EE + lane] = acc[r];
}

// ---------------------------------------------------------------------------
// Kernel 2: edge reduce (e-packed f32x2) + per-b last-block final reduction.
// Grid (8,8,8): jb, b, s. 256 threads. smem: interleaved (s0,s1,w0,w1) quads
// so the inner loop needs one LDS.128; explicit register double-buffer.
// ---------------------------------------------------------------------------
__global__ __launch_bounds__(256) void edge_reduce_kernel(
    const float* __restrict__ Wr,
    const float* __restrict__ br,
    float* __restrict__ part,
    float* __restrict__ out)
{
    const int jb = blockIdx.x;
    const int b  = blockIdx.y;
    const int s  = blockIdx.z;
    const int tid  = threadIdx.x;
    const int lane = tid & 31;
    const int w    = tid >> 5;                  // warp 0..7
    const int le   = lane & 15;                 // e-pair index (e = 2*le)
    const int jg   = lane >> 4;                 // j-group within warp

    __shared__ float4 q_sh [IT * 16];           // 16 KB: (s0,s1,w0,w1) quads
    __shared__ float  dst_sh[JT * EE];          // 8 KB
    __shared__ int    s_last;

    // stage: dst (2 float4/thread); src+Wr interleaved into quads
    {
        const float4* dst_g = (const float4*)(g_dstb + (b * NN + jb * JT) * EE);
        const float4* src_g = (const float4*)(g_src  + (b * NN + s  * IT) * EE);
        const float4* wr_g  = (const float4*)(Wr + s * IT * EE);
        #pragma unroll
        for (int k = 0; k < 2; k++) {
            const int idx = k * 256 + tid;      // 0..511
            ((float4*)dst_sh)[idx] = dst_g[idx];
            float4 sv = src_g[idx];             // row = idx>>3, e-group idx&7
            float4 wv = wr_g [idx];
            const int row = idx >> 3, c8 = idx & 7;
            q_sh[row * 16 + c8 * 2    ] = make_float4(sv.x, sv.y, wv.x, wv.y);
            q_sh[row * 16 + c8 * 2 + 1] = make_float4(sv.z, sv.w, wv.z, wv.w);
        }
    }
    __syncthreads();

    const int jl0 = w * 8 + jg * 4;             // this thread's first j (of 4)
    F2U dreg2[4], acc2[4];
    #pragma unroll
    for (int r = 0; r < 4; r++) {
        dreg2[r].f = *(const float2*)&dst_sh[(jl0 + r) * EE + 2 * le];
        acc2[r].u  = 0ull;
    }

    // double-buffered inner loop: 1 LDS.128 + 16 pipe issues per i
    float4 cur = q_sh[le];
    #pragma unroll 4
    for (int i = 0; i < IT; i++) {
        const float4 nxt = (i + 1 < IT) ? q_sh[(i + 1) * 16 + le] : cur;
        F2U sv2, wv2;
        sv2.f.x = cur.x; sv2.f.y = cur.y;
        wv2.f.x = cur.z; wv2.f.y = cur.w;
        #pragma unroll
        for (int r = 0; r < 4; r++) {
            F2U t; t.u = add2(sv2.u, dreg2[r].u);       // FADD2
            t.f.x = fmaxf(t.f.x, 0.0f);                 // FMNMX (alu pipe)
            t.f.y = fmaxf(t.f.y, 0.0f);
            acc2[r].u = fma2(t.u, wv2.u, acc2[r].u);    // FFMA2
        }
        cur = nxt;
    }

    // collapse e-pair, reduce over the 16 lanes of each half-warp
    float acc[4];
    #pragma unroll
    for (int r = 0; r < 4; r++) {
        acc[r] = acc2[r].f.x + acc2[r].f.y;
        #pragma unroll
        for (int off = 8; off; off >>= 1)
            acc[r] += __shfl_xor_sync(0xFFFFFFFFu, acc[r], off);
    }

    if (le == 0) {                              // lanes 0 and 16 write
        const int j = jb * JT + jl0;
        #pragma unroll
        for (int r = 0; r < 4; r++)
            part[(b * NN + j + r) * SS + s] = acc[r];
    }

    // ---- completion protocol: last block of this b does b's final reduce ----
    __threadfence();
    __syncthreads();
    if (tid == 0) {
        unsigned int cnt = atomicAdd(&g_done[b], 1u) + 1u;   // monotonic
        s_last = ((cnt & 63u) == 0u);           // 64 blocks per b per launch
    }
    __syncthreads();
    if (!s_last) return;
    __threadfence();                            // acquire partials

    const float brv = br[0];
    #pragma unroll
    for (int k = 0; k < 2; k++) {
        const int j = k * 256 + tid;            // 0..511
        const float4* p4 = (const float4*)(part + (b * NN + j) * SS);
        float4 a = p4[0];
        float4 c = p4[1];
        out[b * NN + j] = (a.x + a.y) + (a.z + a.w)
                        + (c.x + c.y) + (c.z + c.w) + brv;
    }
}

// ---------------------------------------------------------------------------
// launch: TWO kernels
// ---------------------------------------------------------------------------
extern "C" void kernel_launch(void* const* d_in, const int* in_sizes, int n_in,
                              void* d_out, int out_size)
{
    const float* x  = (const float*)d_in[0];   // (8,512,64)
    const float* We = (const float*)d_in[1];   // (128,32)
    const float* be = (const float*)d_in[2];   // (32,)
    const float* Wr = (const float*)d_in[3];   // (16384,1)
    const float* br = (const float*)d_in[4];   // (1,)
    float* out = (float*)d_out;                // (8,512,1)

    float* partp;
    cudaGetSymbolAddress((void**)&partp, g_part);

    proj_kernel<<<BB * NN / RPB, 256>>>(x, We, be);

    dim3 grid(NN / JT, BB, SS);                // (8,8,8) = 512 blocks
    edge_reduce_kernel<<<grid, 256>>>(Wr, br, partp, out);
}